// round 2
// baseline (speedup 1.0000x reference)
#include <cuda_runtime.h>
#include <math.h>

#define B 4
#define L 2048
#define D 2048
#define LC 64          // L-chunks for pass-1 partial reduction
#define LPC (L/LC)     // 32 rows per chunk
#define IC 32          // i-chunks for column-term GEMV
#define IPC (D/IC)     // 64
#define DT_STEP 0.01f
#define DEG 8

// ---- scratch (device globals, no allocation allowed) ----
__device__ float g_partial[B*LC*D];   // 2 MB  pass-1 partial sums [b][chunk][d]
__device__ float g_xmean[B*D];        // 32 KB
__device__ float g_t[B*D];            // 32 KB  t = H @ x_mean
__device__ float g_colpart[IC*B*D];   // 1 MB   partial J_u^T t terms
__device__ float g_delta[B*D];        // 32 KB  broadcast row update

// ============ Pass 1: partial column sums over L-chunks ============
__global__ void k_partial(const float* __restrict__ x) {
    int dt = blockIdx.x;            // d-tile: 0..1 (1024 d each)
    int lc = blockIdx.y;            // l-chunk: 0..63
    int b  = blockIdx.z;
    int d  = dt*1024 + threadIdx.x*4;
    float4 acc = make_float4(0.f,0.f,0.f,0.f);
    size_t base = ((size_t)b*L + (size_t)lc*LPC)*D + d;
    const float4* xp = (const float4*)x;
    #pragma unroll 4
    for (int l = 0; l < LPC; ++l) {
        float4 v = xp[(base + (size_t)l*D) >> 2];
        acc.x += v.x; acc.y += v.y; acc.z += v.z; acc.w += v.w;
    }
    *(float4*)&g_partial[(size_t)(b*LC + lc)*D + d] = acc;
}

// ============ Finalize mean ============
__global__ void k_mean() {
    int idx = blockIdx.x*256 + threadIdx.x;   // 0..B*D-1
    int b = idx >> 11;
    int d = idx & (D-1);
    float s = 0.f;
    #pragma unroll 8
    for (int c = 0; c < LC; ++c)
        s += g_partial[(size_t)(b*LC + c)*D + d];
    g_xmean[idx] = s * (1.0f / (float)L);
}

// ============ GEMV 1: t[b,i] = sum_j h[i,j] * xmean[b,j] ============
__global__ void k_gemv1(const float* __restrict__ h) {
    __shared__ float s_m[B*D];   // 32 KB
    for (int i = threadIdx.x; i < (B*D)/4; i += 256)
        ((float4*)s_m)[i] = ((const float4*)g_xmean)[i];
    __syncthreads();
    int warp = threadIdx.x >> 5, lane = threadIdx.x & 31;
    int row  = blockIdx.x*8 + warp;
    const float4* hp = (const float4*)(h + (size_t)row*D);
    float a0=0.f, a1=0.f, a2=0.f, a3=0.f;
    #pragma unroll 4
    for (int jj = 0; jj < D/128; ++jj) {
        int j4 = jj*32 + lane;
        float4 hv = hp[j4];
        int j = j4*4;
        float4 m0 = *(const float4*)&s_m[0*D + j];
        float4 m1 = *(const float4*)&s_m[1*D + j];
        float4 m2 = *(const float4*)&s_m[2*D + j];
        float4 m3 = *(const float4*)&s_m[3*D + j];
        a0 += hv.x*m0.x + hv.y*m0.y + hv.z*m0.z + hv.w*m0.w;
        a1 += hv.x*m1.x + hv.y*m1.y + hv.z*m1.z + hv.w*m1.w;
        a2 += hv.x*m2.x + hv.y*m2.y + hv.z*m2.z + hv.w*m2.w;
        a3 += hv.x*m3.x + hv.y*m3.y + hv.z*m3.z + hv.w*m3.w;
    }
    #pragma unroll
    for (int off = 16; off; off >>= 1) {
        a0 += __shfl_xor_sync(0xFFFFFFFFu, a0, off);
        a1 += __shfl_xor_sync(0xFFFFFFFFu, a1, off);
        a2 += __shfl_xor_sync(0xFFFFFFFFu, a2, off);
        a3 += __shfl_xor_sync(0xFFFFFFFFu, a3, off);
    }
    if (lane == 0) {
        g_t[0*D + row] = a0;
        g_t[1*D + row] = a1;
        g_t[2*D + row] = a2;
        g_t[3*D + row] = a3;
    }
}

// ============ GEMV 2a: column-term partials: sum_{i in chunk} t[b,i]*ju[i,k] ============
__global__ void k_col(const float* __restrict__ ju) {
    __shared__ float s_t[B*IPC];
    int ic = blockIdx.y;
    int i0 = ic*IPC;
    for (int i = threadIdx.x; i < B*IPC; i += 256) {
        int b = i / IPC, ii = i % IPC;
        s_t[i] = g_t[b*D + i0 + ii];
    }
    __syncthreads();
    int k = blockIdx.x*256 + threadIdx.x;
    float a0=0.f, a1=0.f, a2=0.f, a3=0.f;
    #pragma unroll 8
    for (int ii = 0; ii < IPC; ++ii) {
        float v = ju[(size_t)(i0 + ii)*D + k];
        a0 += s_t[0*IPC + ii]*v;
        a1 += s_t[1*IPC + ii]*v;
        a2 += s_t[2*IPC + ii]*v;
        a3 += s_t[3*IPC + ii]*v;
    }
    g_colpart[(size_t)(ic*B + 0)*D + k] = a0;
    g_colpart[(size_t)(ic*B + 1)*D + k] = a1;
    g_colpart[(size_t)(ic*B + 2)*D + k] = a2;
    g_colpart[(size_t)(ic*B + 3)*D + k] = a3;
}

// ============ GEMV 2b + finalize delta ============
// delta[b,k] = DT * ( sum_i t[b,i]*ju[k,i]  -  sum_i t[b,i]*ju[i,k]  -  softplus(r[k])*t[b,k] )
__global__ void k_delta(const float* __restrict__ ju, const float* __restrict__ rd) {
    __shared__ float s_t[B*D];
    for (int i = threadIdx.x; i < (B*D)/4; i += 256)
        ((float4*)s_t)[i] = ((const float4*)g_t)[i];
    __syncthreads();
    int warp = threadIdx.x >> 5, lane = threadIdx.x & 31;
    int k = blockIdx.x*8 + warp;
    const float4* jp = (const float4*)(ju + (size_t)k*D);
    float a0=0.f, a1=0.f, a2=0.f, a3=0.f;
    #pragma unroll 4
    for (int jj = 0; jj < D/128; ++jj) {
        int j4 = jj*32 + lane;
        float4 jv = jp[j4];
        int j = j4*4;
        float4 m0 = *(const float4*)&s_t[0*D + j];
        float4 m1 = *(const float4*)&s_t[1*D + j];
        float4 m2 = *(const float4*)&s_t[2*D + j];
        float4 m3 = *(const float4*)&s_t[3*D + j];
        a0 += jv.x*m0.x + jv.y*m0.y + jv.z*m0.z + jv.w*m0.w;
        a1 += jv.x*m1.x + jv.y*m1.y + jv.z*m1.z + jv.w*m1.w;
        a2 += jv.x*m2.x + jv.y*m2.y + jv.z*m2.z + jv.w*m2.w;
        a3 += jv.x*m3.x + jv.y*m3.y + jv.z*m3.z + jv.w*m3.w;
    }
    #pragma unroll
    for (int off = 16; off; off >>= 1) {   // butterfly: all lanes get full sum
        a0 += __shfl_xor_sync(0xFFFFFFFFu, a0, off);
        a1 += __shfl_xor_sync(0xFFFFFFFFu, a1, off);
        a2 += __shfl_xor_sync(0xFFFFFFFFu, a2, off);
        a3 += __shfl_xor_sync(0xFFFFFFFFu, a3, off);
    }
    if (lane < 4) {
        int b = lane;
        float rowacc = (b==0)?a0 : (b==1)?a1 : (b==2)?a2 : a3;
        float col = 0.f;
        #pragma unroll 8
        for (int ic = 0; ic < IC; ++ic)
            col += g_colpart[(size_t)(ic*B + b)*D + k];
        float rv = rd[k];
        float r = (rv > 20.f) ? rv : log1pf(expf(rv));   // softplus
        g_delta[b*D + k] = DT_STEP * (rowacc - col - r*s_t[b*D + k]);
    }
}

// ============ Chebyshev helper ============
__device__ __forceinline__ float cheb_eval(float xn, const float* __restrict__ c) {
    float tp = 1.f, tc = xn;
    float o = fmaf(c[1], xn, c[0]);
    #pragma unroll
    for (int i = 2; i <= DEG; ++i) {
        float tn = fmaf(2.f*xn, tc, -tp);
        o = fmaf(c[i], tn, o);
        tp = tc; tc = tn;
    }
    return o;
}

// ============ Main fused pass: y=x+delta, row L2 norm, Chebyshev, out ============
__global__ void k_main(const float* __restrict__ x, const float* __restrict__ coef,
                       float* __restrict__ out) {
    __shared__ float s_delta[D];   // 8 KB
    __shared__ float s_c[DEG+1];
    __shared__ float s_red[9];
    int l = blockIdx.x, b = blockIdx.y;
    int tid = threadIdx.x;
    if (tid <= DEG) s_c[tid] = coef[tid];
    for (int i = tid; i < D/4; i += 256)
        ((float4*)s_delta)[i] = ((const float4*)&g_delta[b*D])[i];
    __syncthreads();

    size_t base = ((size_t)b*L + l)*D;
    const float4* xp = (const float4*)(x + base);
    float4*       op = (float4*)(out + base);

    float4 y0 = xp[tid];
    float4 d0 = ((const float4*)s_delta)[tid];
    y0.x += d0.x; y0.y += d0.y; y0.z += d0.z; y0.w += d0.w;
    float4 y1 = xp[tid + 256];
    float4 d1 = ((const float4*)s_delta)[tid + 256];
    y1.x += d1.x; y1.y += d1.y; y1.z += d1.z; y1.w += d1.w;

    float sq = y0.x*y0.x + y0.y*y0.y + y0.z*y0.z + y0.w*y0.w
             + y1.x*y1.x + y1.y*y1.y + y1.z*y1.z + y1.w*y1.w;
    #pragma unroll
    for (int off = 16; off; off >>= 1)
        sq += __shfl_xor_sync(0xFFFFFFFFu, sq, off);
    int warp = tid >> 5, lane = tid & 31;
    if (lane == 0) s_red[warp] = sq;
    __syncthreads();
    if (warp == 0) {
        float v = (lane < 8) ? s_red[lane] : 0.f;
        #pragma unroll
        for (int off = 4; off; off >>= 1)
            v += __shfl_xor_sync(0xFFFFFFFFu, v, off);
        if (lane == 0) s_red[8] = v;
    }
    __syncthreads();
    float inv = rsqrtf(fmaxf(s_red[8], 1e-8f));

    float4 r0, r1;
    r0.x = y0.x + 0.1f*cheb_eval(y0.x*inv, s_c);
    r0.y = y0.y + 0.1f*cheb_eval(y0.y*inv, s_c);
    r0.z = y0.z + 0.1f*cheb_eval(y0.z*inv, s_c);
    r0.w = y0.w + 0.1f*cheb_eval(y0.w*inv, s_c);
    r1.x = y1.x + 0.1f*cheb_eval(y1.x*inv, s_c);
    r1.y = y1.y + 0.1f*cheb_eval(y1.y*inv, s_c);
    r1.z = y1.z + 0.1f*cheb_eval(y1.z*inv, s_c);
    r1.w = y1.w + 0.1f*cheb_eval(y1.w*inv, s_c);
    op[tid]       = r0;
    op[tid + 256] = r1;
}

extern "C" void kernel_launch(void* const* d_in, const int* in_sizes, int n_in,
                              void* d_out, int out_size) {
    const float* x   = (const float*)d_in[0];   // [B, L, D]
    const float* ju  = (const float*)d_in[1];   // [D, D]
    const float* rd  = (const float*)d_in[2];   // [D]
    const float* hp  = (const float*)d_in[3];   // [D, D]
    const float* cf  = (const float*)d_in[4];   // [9]
    float* out = (float*)d_out;
    (void)in_sizes; (void)n_in; (void)out_size;

    k_partial<<<dim3(2, LC, B), 256>>>(x);
    k_mean<<<(B*D)/256, 256>>>();
    k_gemv1<<<D/8, 256>>>(hp);
    k_col<<<dim3(D/256, IC), 256>>>(ju);
    k_delta<<<D/8, 256>>>(ju, rd);
    k_main<<<dim3(L, B), 256>>>(x, cf, out);
}